// round 2
// baseline (speedup 1.0000x reference)
#include <cuda_runtime.h>
#include <math.h>
#include <stdint.h>

// NGP multiresolution hash-grid interpolation encoding.
// B=262144 points, DIM=3, L=16 levels, T=19 (2^19 entries/level), F=2 features.
// out[b, l*2+f] = sum_{v=0..7} w_v * tables[l, hash(corner_v) & MASK, f]
//
// Key optimization: PRIMES[0]==1, so the x-corner pair (gx, gx+1) hashes to
// {i, i^1} whenever gx is even -> one aligned float4 load replaces two float2
// gathers (predicated per-lane, no divergence), cutting L1tex wavefronts ~25%.

#define NGP_L 16
#define NGP_T 19
#define NGP_MASK ((1u << NGP_T) - 1u)
#define NGP_P1 2654435761u
#define NGP_P2 805459861u

struct ResParams { float r[NGP_L]; };

// Predicated pair gather: if ev, load the aligned float4 covering {i0, i0^1};
// else load two independent float2 gathers. Selection fixes the ordering.
__device__ __forceinline__ void pair_load(const float2* __restrict__ tbl,
                                          unsigned i0, unsigned i1, unsigned ev,
                                          float2& v0, float2& v1)
{
    float qx, qy, qz, qw;   // even path: table entries {2k, 2k+1}
    float ax, ay, bx, by;   // odd path: entries i0, i1
    const float4* p4 = reinterpret_cast<const float4*>(tbl) + (i0 >> 1);
    const float2* p0 = tbl + i0;
    const float2* p1 = tbl + i1;
    asm("{\n\t"
        ".reg .pred p;\n\t"
        "setp.ne.u32 p, %8, 0;\n\t"
        "@p  ld.global.nc.v4.f32 {%0,%1,%2,%3}, [%9];\n\t"
        "@!p ld.global.nc.v2.f32 {%4,%5}, [%10];\n\t"
        "@!p ld.global.nc.v2.f32 {%6,%7}, [%11];\n\t"
        "}"
        : "=f"(qx), "=f"(qy), "=f"(qz), "=f"(qw),
          "=f"(ax), "=f"(ay), "=f"(bx), "=f"(by)
        : "r"(ev), "l"(p4), "l"(p0), "l"(p1));

    bool hi0 = (i0 & 1u) != 0u;            // is corner0 the odd entry of the pair?
    float e0x = hi0 ? qz : qx, e0y = hi0 ? qw : qy;
    float e1x = hi0 ? qx : qz, e1y = hi0 ? qy : qw;
    bool e = ev != 0u;
    v0.x = e ? e0x : ax;  v0.y = e ? e0y : ay;
    v1.x = e ? e1x : bx;  v1.y = e ? e1y : by;
}

__global__ void __launch_bounds__(256) ngp_enc_kernel(
    const float* __restrict__ x,
    const float2* __restrict__ tables,
    float2* __restrict__ out,
    ResParams rp, int npts)
{
    int t = blockIdx.x * 256 + threadIdx.x;
    int b = t >> 4;
    int l = t & 15;
    if (b >= npts) return;

    float res = rp.r[l];

    float x0 = __ldg(x + 3 * b + 0);
    float x1 = __ldg(x + 3 * b + 1);
    float x2 = __ldg(x + 3 * b + 2);

    float sx = x0 * res;
    float sy = x1 * res;
    float sz = x2 * res;

    float fx = floorf(sx);
    float fy = floorf(sy);
    float fz = floorf(sz);

    unsigned gx = (unsigned)fx;
    unsigned gy = (unsigned)fy;
    unsigned gz = (unsigned)fz;

    float tx = sx - fx;
    float ty = sy - fy;
    float tz = sz - fz;

    // hash partials: dim0 prime = 1
    unsigned hx0 = gx;
    unsigned hx1 = gx + 1u;
    unsigned hy0 = gy * NGP_P1;
    unsigned hy1 = hy0 + NGP_P1;
    unsigned hz0 = gz * NGP_P2;
    unsigned hz1 = hz0 + NGP_P2;

    const float2* __restrict__ tbl = tables + ((size_t)l << NGP_T);

    // 8 corner indices (corner v: bit0->x, bit1->y, bit2->z)
    unsigned i0 = (hx0 ^ hy0 ^ hz0) & NGP_MASK;
    unsigned i1 = (hx1 ^ hy0 ^ hz0) & NGP_MASK;
    unsigned i2 = (hx0 ^ hy1 ^ hz0) & NGP_MASK;
    unsigned i3 = (hx1 ^ hy1 ^ hz0) & NGP_MASK;
    unsigned i4 = (hx0 ^ hy0 ^ hz1) & NGP_MASK;
    unsigned i5 = (hx1 ^ hy0 ^ hz1) & NGP_MASK;
    unsigned i6 = (hx0 ^ hy1 ^ hz1) & NGP_MASK;
    unsigned i7 = (hx1 ^ hy1 ^ hz1) & NGP_MASK;

    unsigned ev = (~gx) & 1u;   // gx even -> x-pairs are {i, i^1}

    // Batch all gathers (predicated float4 when gx even) for high MLP
    float2 v0, v1, v2, v3, v4, v5, v6, v7;
    pair_load(tbl, i0, i1, ev, v0, v1);
    pair_load(tbl, i2, i3, ev, v2, v3);
    pair_load(tbl, i4, i5, ev, v4, v5);
    pair_load(tbl, i6, i7, ev, v6, v7);

    float wx0 = 1.0f - tx;
    float wy0 = 1.0f - ty;
    float wz0 = 1.0f - tz;

    float w00 = wx0 * wy0;   // x0 y0
    float w10 = tx  * wy0;   // x1 y0
    float w01 = wx0 * ty;    // x0 y1
    float w11 = tx  * ty;    // x1 y1

    float a0 = 0.0f, a1 = 0.0f;
    float w;
    w = w00 * wz0; a0 = fmaf(w, v0.x, a0); a1 = fmaf(w, v0.y, a1);
    w = w10 * wz0; a0 = fmaf(w, v1.x, a0); a1 = fmaf(w, v1.y, a1);
    w = w01 * wz0; a0 = fmaf(w, v2.x, a0); a1 = fmaf(w, v2.y, a1);
    w = w11 * wz0; a0 = fmaf(w, v3.x, a0); a1 = fmaf(w, v3.y, a1);
    w = w00 * tz;  a0 = fmaf(w, v4.x, a0); a1 = fmaf(w, v4.y, a1);
    w = w10 * tz;  a0 = fmaf(w, v5.x, a0); a1 = fmaf(w, v5.y, a1);
    w = w01 * tz;  a0 = fmaf(w, v6.x, a0); a1 = fmaf(w, v6.y, a1);
    w = w11 * tz;  a0 = fmaf(w, v7.x, a0); a1 = fmaf(w, v7.y, a1);

    out[(size_t)b * 16 + l] = make_float2(a0, a1);
}

extern "C" void kernel_launch(void* const* d_in, const int* in_sizes, int n_in,
                              void* d_out, int out_size)
{
    const float* x = (const float*)d_in[0];
    const float2* tables = (const float2*)d_in[1];
    float2* out = (float2*)d_out;
    int npts = in_sizes[0] / 3;

    // Replicate numpy's RES computation bit-for-bit in float64 using the same
    // glibc libm the reference uses on this host (incl. numpy's pow shortcuts
    // for small integer exponents). RES sits exactly on integers at levels
    // 0,3,6,9,12,15 so hardcoding risks off-by-one in floor().
    ResParams rp;
    double bb = exp((log(512.0) - log(16.0)) / 15.0);
    for (int l = 0; l < NGP_L; l++) {
        double p;
        if (l == 0)      p = 1.0;
        else if (l == 1) p = bb;
        else if (l == 2) p = bb * bb;     // numpy npy_pow shortcut y==2 -> x*x
        else             p = pow(bb, (double)l);
        rp.r[l] = (float)floor(16.0 * p);
    }

    int total = npts * 16;
    int blocks = (total + 255) / 256;
    ngp_enc_kernel<<<blocks, 256>>>(x, tables, out, rp, npts);
}

// round 3
// speedup vs baseline: 1.4299x; 1.4299x over previous
#include <cuda_runtime.h>
#include <math.h>
#include <stdint.h>

// NGP multiresolution hash-grid interpolation encoding.
// B=262144 points, DIM=3, L=16 levels, T=19 (2^19 entries/level), F=2 features.
// out[b, l*2+f] = sum_{v=0..7} w_v * tables[l, hash(corner_v) & MASK, f]
//
// Round-1 structure (best known: 83us, L1tex-bound at 85.5%) + persistent
// grid-stride CTAs to eliminate ~13 wave transitions (~17us of slack).

#define NGP_L 16
#define NGP_T 19
#define NGP_MASK ((1u << NGP_T) - 1u)
#define NGP_P1 2654435761u
#define NGP_P2 805459861u

struct ResParams { float r[NGP_L]; };

__global__ void __launch_bounds__(256, 8) ngp_enc_kernel(
    const float* __restrict__ x,
    const float2* __restrict__ tables,
    float2* __restrict__ out,
    ResParams rp, int total)
{
    int stride = gridDim.x * 256;
    for (int t = blockIdx.x * 256 + threadIdx.x; t < total; t += stride) {
        int b = t >> 4;
        int l = t & 15;

        float res = rp.r[l];

        float x0 = __ldg(x + 3 * b + 0);
        float x1 = __ldg(x + 3 * b + 1);
        float x2 = __ldg(x + 3 * b + 2);

        float sx = x0 * res;
        float sy = x1 * res;
        float sz = x2 * res;

        float fx = floorf(sx);
        float fy = floorf(sy);
        float fz = floorf(sz);

        unsigned gx = (unsigned)fx;
        unsigned gy = (unsigned)fy;
        unsigned gz = (unsigned)fz;

        float tx = sx - fx;
        float ty = sy - fy;
        float tz = sz - fz;

        // hash partials: dim0 prime = 1
        unsigned hx0 = gx;
        unsigned hx1 = gx + 1u;
        unsigned hy0 = gy * NGP_P1;
        unsigned hy1 = hy0 + NGP_P1;
        unsigned hz0 = gz * NGP_P2;
        unsigned hz1 = hz0 + NGP_P2;

        const float2* __restrict__ tbl = tables + ((size_t)l << NGP_T);

        // 8 corner indices (corner v: bit0->x, bit1->y, bit2->z)
        unsigned i0 = (hx0 ^ hy0 ^ hz0) & NGP_MASK;
        unsigned i1 = (hx1 ^ hy0 ^ hz0) & NGP_MASK;
        unsigned i2 = (hx0 ^ hy1 ^ hz0) & NGP_MASK;
        unsigned i3 = (hx1 ^ hy1 ^ hz0) & NGP_MASK;
        unsigned i4 = (hx0 ^ hy0 ^ hz1) & NGP_MASK;
        unsigned i5 = (hx1 ^ hy0 ^ hz1) & NGP_MASK;
        unsigned i6 = (hx0 ^ hy1 ^ hz1) & NGP_MASK;
        unsigned i7 = (hx1 ^ hy1 ^ hz1) & NGP_MASK;

        // batch the 8 gathers for MLP=8 (hide L2 latency)
        float2 v0 = __ldg(tbl + i0);
        float2 v1 = __ldg(tbl + i1);
        float2 v2 = __ldg(tbl + i2);
        float2 v3 = __ldg(tbl + i3);
        float2 v4 = __ldg(tbl + i4);
        float2 v5 = __ldg(tbl + i5);
        float2 v6 = __ldg(tbl + i6);
        float2 v7 = __ldg(tbl + i7);

        float wx0 = 1.0f - tx;
        float wy0 = 1.0f - ty;
        float wz0 = 1.0f - tz;

        float w00 = wx0 * wy0;   // x0 y0
        float w10 = tx  * wy0;   // x1 y0
        float w01 = wx0 * ty;    // x0 y1
        float w11 = tx  * ty;    // x1 y1

        float a0 = 0.0f, a1 = 0.0f;
        float w;
        w = w00 * wz0; a0 = fmaf(w, v0.x, a0); a1 = fmaf(w, v0.y, a1);
        w = w10 * wz0; a0 = fmaf(w, v1.x, a0); a1 = fmaf(w, v1.y, a1);
        w = w01 * wz0; a0 = fmaf(w, v2.x, a0); a1 = fmaf(w, v2.y, a1);
        w = w11 * wz0; a0 = fmaf(w, v3.x, a0); a1 = fmaf(w, v3.y, a1);
        w = w00 * tz;  a0 = fmaf(w, v4.x, a0); a1 = fmaf(w, v4.y, a1);
        w = w10 * tz;  a0 = fmaf(w, v5.x, a0); a1 = fmaf(w, v5.y, a1);
        w = w01 * tz;  a0 = fmaf(w, v6.x, a0); a1 = fmaf(w, v6.y, a1);
        w = w11 * tz;  a0 = fmaf(w, v7.x, a0); a1 = fmaf(w, v7.y, a1);

        out[(size_t)b * 16 + l] = make_float2(a0, a1);
    }
}

extern "C" void kernel_launch(void* const* d_in, const int* in_sizes, int n_in,
                              void* d_out, int out_size)
{
    const float* x = (const float*)d_in[0];
    const float2* tables = (const float2*)d_in[1];
    float2* out = (float2*)d_out;
    int npts = in_sizes[0] / 3;

    // Replicate numpy's RES computation bit-for-bit in float64 using the same
    // glibc libm the reference uses on this host (incl. numpy's pow shortcuts
    // for small integer exponents). RES sits exactly on integers at levels
    // 0,3,6,9,12,15 so hardcoding risks off-by-one in floor().
    ResParams rp;
    double bb = exp((log(512.0) - log(16.0)) / 15.0);
    for (int l = 0; l < NGP_L; l++) {
        double p;
        if (l == 0)      p = 1.0;
        else if (l == 1) p = bb;
        else if (l == 2) p = bb * bb;     // numpy npy_pow shortcut y==2 -> x*x
        else             p = pow(bb, (double)l);
        rp.r[l] = (float)floor(16.0 * p);
    }

    int total = npts * 16;

    // Persistent grid: exactly one wave (SMs x 8 CTAs of 256 threads),
    // grid-stride loop -> no wave-transition overhead, no tail wave.
    int dev = 0, sms = 148;
    cudaGetDevice(&dev);
    cudaDeviceGetAttribute(&sms, cudaDevAttrMultiProcessorCount, dev);
    int blocks = sms * 8;
    int needed = (total + 255) / 256;
    if (blocks > needed) blocks = needed;

    ngp_enc_kernel<<<blocks, 256>>>(x, tables, out, rp, total);
}

// round 6
// speedup vs baseline: 1.4385x; 1.0060x over previous
#include <cuda_runtime.h>
#include <math.h>
#include <stdint.h>

// NGP multiresolution hash-grid interpolation encoding, with Morton bucket
// sort so warp lanes are spatially adjacent -> gather cache-line sharing.
// B=262144 points, DIM=3, L=16 levels, T=19, F=2.

#define NGP_L 16
#define NGP_T 19
#define NGP_MASK ((1u << NGP_T) - 1u)
#define NGP_P1 2654435761u
#define NGP_P2 805459861u
#define BMAX 262144
#define NB 4096            // 16^3 Morton buckets

struct ResParams { float r[NGP_L]; };

__device__ unsigned g_hist[NB];
__device__ unsigned g_off[NB];
__device__ float4   g_pk[BMAX];          // sorted (x, y, z, orig_idx_bits)
__device__ float2   g_tmp[NGP_L * BMAX]; // level-major results, sorted order

__device__ __forceinline__ unsigned spread3(unsigned v) {
    // 4-bit v -> bits at positions 0,3,6,9
    return (v & 1u) | ((v & 2u) << 2) | ((v & 4u) << 4) | ((v & 8u) << 6);
}

__device__ __forceinline__ unsigned bucket_of(float x0, float x1, float x2) {
    unsigned bx = (unsigned)(x0 * 16.0f); if (bx > 15u) bx = 15u;
    unsigned by = (unsigned)(x1 * 16.0f); if (by > 15u) by = 15u;
    unsigned bz = (unsigned)(x2 * 16.0f); if (bz > 15u) bz = 15u;
    return spread3(bx) | (spread3(by) << 1) | (spread3(bz) << 2);
}

__global__ void k_hist(const float* __restrict__ x, int n) {
    int b = blockIdx.x * 256 + threadIdx.x;
    if (b >= n) return;
    atomicAdd(&g_hist[bucket_of(x[3*b], x[3*b+1], x[3*b+2])], 1u);
}

// exclusive scan of g_hist (4096 = 1024 threads x 4) -> g_off
__global__ void k_scan() {
    __shared__ unsigned s[1024];
    int t = threadIdx.x;
    unsigned h0 = g_hist[4*t], h1 = g_hist[4*t+1], h2 = g_hist[4*t+2], h3 = g_hist[4*t+3];
    s[t] = h0 + h1 + h2 + h3;
    __syncthreads();
    for (int d = 1; d < 1024; d <<= 1) {
        unsigned v = (t >= d) ? s[t-d] : 0u;
        __syncthreads();
        s[t] += v;
        __syncthreads();
    }
    unsigned excl = (t == 0) ? 0u : s[t-1];
    g_off[4*t]   = excl;
    g_off[4*t+1] = excl + h0;
    g_off[4*t+2] = excl + h0 + h1;
    g_off[4*t+3] = excl + h0 + h1 + h2;
}

__global__ void k_scatter(const float* __restrict__ x, int n) {
    int b = blockIdx.x * 256 + threadIdx.x;
    if (b >= n) return;
    float x0 = x[3*b], x1 = x[3*b+1], x2 = x[3*b+2];
    unsigned p = atomicAdd(&g_off[bucket_of(x0, x1, x2)], 1u);
    g_pk[p] = make_float4(x0, x1, x2, __uint_as_float((unsigned)b));
}

// Main: thread = one sorted point, loops all 16 levels. Warp = 32 adjacent
// points -> gather line sharing. Writes level-major tmp (coalesced).
__global__ void __launch_bounds__(256) k_main(
    const float2* __restrict__ tables, ResParams rp, int n)
{
    int pos = blockIdx.x * 256 + threadIdx.x;
    if (pos >= n) return;
    float4 pk = g_pk[pos];
    float x0 = pk.x, x1 = pk.y, x2 = pk.z;

    #pragma unroll 1
    for (int l = 0; l < NGP_L; l++) {
        float res = rp.r[l];
        float sx = x0 * res, sy = x1 * res, sz = x2 * res;
        float fx = floorf(sx), fy = floorf(sy), fz = floorf(sz);
        unsigned gx = (unsigned)fx, gy = (unsigned)fy, gz = (unsigned)fz;
        float tx = sx - fx, ty = sy - fy, tz = sz - fz;

        unsigned hx0 = gx,            hx1 = gx + 1u;
        unsigned hy0 = gy * NGP_P1,   hy1 = hy0 + NGP_P1;
        unsigned hz0 = gz * NGP_P2,   hz1 = hz0 + NGP_P2;

        const float2* __restrict__ tbl = tables + ((size_t)l << NGP_T);

        unsigned i0 = (hx0 ^ hy0 ^ hz0) & NGP_MASK;
        unsigned i1 = (hx1 ^ hy0 ^ hz0) & NGP_MASK;
        unsigned i2 = (hx0 ^ hy1 ^ hz0) & NGP_MASK;
        unsigned i3 = (hx1 ^ hy1 ^ hz0) & NGP_MASK;
        unsigned i4 = (hx0 ^ hy0 ^ hz1) & NGP_MASK;
        unsigned i5 = (hx1 ^ hy0 ^ hz1) & NGP_MASK;
        unsigned i6 = (hx0 ^ hy1 ^ hz1) & NGP_MASK;
        unsigned i7 = (hx1 ^ hy1 ^ hz1) & NGP_MASK;

        float2 v0 = __ldg(tbl + i0);
        float2 v1 = __ldg(tbl + i1);
        float2 v2 = __ldg(tbl + i2);
        float2 v3 = __ldg(tbl + i3);
        float2 v4 = __ldg(tbl + i4);
        float2 v5 = __ldg(tbl + i5);
        float2 v6 = __ldg(tbl + i6);
        float2 v7 = __ldg(tbl + i7);

        float wx0 = 1.0f - tx, wy0 = 1.0f - ty, wz0 = 1.0f - tz;
        float w00 = wx0 * wy0, w10 = tx * wy0, w01 = wx0 * ty, w11 = tx * ty;

        float a0 = 0.0f, a1 = 0.0f, w;
        w = w00 * wz0; a0 = fmaf(w, v0.x, a0); a1 = fmaf(w, v0.y, a1);
        w = w10 * wz0; a0 = fmaf(w, v1.x, a0); a1 = fmaf(w, v1.y, a1);
        w = w01 * wz0; a0 = fmaf(w, v2.x, a0); a1 = fmaf(w, v2.y, a1);
        w = w11 * wz0; a0 = fmaf(w, v3.x, a0); a1 = fmaf(w, v3.y, a1);
        w = w00 * tz;  a0 = fmaf(w, v4.x, a0); a1 = fmaf(w, v4.y, a1);
        w = w10 * tz;  a0 = fmaf(w, v5.x, a0); a1 = fmaf(w, v5.y, a1);
        w = w01 * tz;  a0 = fmaf(w, v6.x, a0); a1 = fmaf(w, v6.y, a1);
        w = w11 * tz;  a0 = fmaf(w, v7.x, a0); a1 = fmaf(w, v7.y, a1);

        g_tmp[(size_t)l * n + pos] = make_float2(a0, a1);
    }
}

// Permute back to original order. Warp handles 32 sorted points; smem
// transpose so each output store instruction's 32 lanes cover exactly one
// point's 128B row -> 1 store wavefront per point.
__global__ void __launch_bounds__(128) k_perm(float* __restrict__ outf, int n)
{
    __shared__ float    sv[4][32][33];
    __shared__ unsigned so[4][32];
    int w = threadIdx.x >> 5, lane = threadIdx.x & 31;
    int pos = blockIdx.x * 128 + threadIdx.x;

    if (pos < n) {
        float4 pk = g_pk[pos];
        so[w][lane] = __float_as_uint(pk.w);
        #pragma unroll
        for (int l = 0; l < NGP_L; l++) {
            float2 v = g_tmp[(size_t)l * n + pos];
            sv[w][lane][2*l]   = v.x;
            sv[w][lane][2*l+1] = v.y;
        }
    }
    __syncwarp();

    int base = blockIdx.x * 128 + w * 32;
    int cnt = n - base; if (cnt > 32) cnt = 32; if (cnt < 0) cnt = 0;
    for (int p = 0; p < cnt; p++) {
        float val  = sv[w][p][lane];
        unsigned o = so[w][p];
        outf[(size_t)o * 32 + lane] = val;
    }
}

// Fallback (round-1 style flat kernel) if npts exceeds scratch capacity.
__global__ void __launch_bounds__(256, 8) ngp_flat_kernel(
    const float* __restrict__ x, const float2* __restrict__ tables,
    float2* __restrict__ out, ResParams rp, int npts)
{
    int t = blockIdx.x * 256 + threadIdx.x;
    int b = t >> 4, l = t & 15;
    if (b >= npts) return;
    float res = rp.r[l];
    float sx = __ldg(x+3*b) * res, sy = __ldg(x+3*b+1) * res, sz = __ldg(x+3*b+2) * res;
    float fx = floorf(sx), fy = floorf(sy), fz = floorf(sz);
    unsigned gx = (unsigned)fx, gy = (unsigned)fy, gz = (unsigned)fz;
    float tx = sx-fx, ty = sy-fy, tz = sz-fz;
    unsigned hx0 = gx, hx1 = gx+1u;
    unsigned hy0 = gy*NGP_P1, hy1 = hy0+NGP_P1;
    unsigned hz0 = gz*NGP_P2, hz1 = hz0+NGP_P2;
    const float2* __restrict__ tbl = tables + ((size_t)l << NGP_T);
    float2 v0 = __ldg(tbl + ((hx0^hy0^hz0)&NGP_MASK));
    float2 v1 = __ldg(tbl + ((hx1^hy0^hz0)&NGP_MASK));
    float2 v2 = __ldg(tbl + ((hx0^hy1^hz0)&NGP_MASK));
    float2 v3 = __ldg(tbl + ((hx1^hy1^hz0)&NGP_MASK));
    float2 v4 = __ldg(tbl + ((hx0^hy0^hz1)&NGP_MASK));
    float2 v5 = __ldg(tbl + ((hx1^hy0^hz1)&NGP_MASK));
    float2 v6 = __ldg(tbl + ((hx0^hy1^hz1)&NGP_MASK));
    float2 v7 = __ldg(tbl + ((hx1^hy1^hz1)&NGP_MASK));
    float wx0 = 1.0f-tx, wy0 = 1.0f-ty, wz0 = 1.0f-tz;
    float w00 = wx0*wy0, w10 = tx*wy0, w01 = wx0*ty, w11 = tx*ty;
    float a0 = 0.f, a1 = 0.f, w;
    w = w00*wz0; a0 = fmaf(w,v0.x,a0); a1 = fmaf(w,v0.y,a1);
    w = w10*wz0; a0 = fmaf(w,v1.x,a0); a1 = fmaf(w,v1.y,a1);
    w = w01*wz0; a0 = fmaf(w,v2.x,a0); a1 = fmaf(w,v2.y,a1);
    w = w11*wz0; a0 = fmaf(w,v3.x,a0); a1 = fmaf(w,v3.y,a1);
    w = w00*tz;  a0 = fmaf(w,v4.x,a0); a1 = fmaf(w,v4.y,a1);
    w = w10*tz;  a0 = fmaf(w,v5.x,a0); a1 = fmaf(w,v5.y,a1);
    w = w01*tz;  a0 = fmaf(w,v6.x,a0); a1 = fmaf(w,v6.y,a1);
    w = w11*tz;  a0 = fmaf(w,v7.x,a0); a1 = fmaf(w,v7.y,a1);
    out[(size_t)b*16 + l] = make_float2(a0, a1);
}

extern "C" void kernel_launch(void* const* d_in, const int* in_sizes, int n_in,
                              void* d_out, int out_size)
{
    const float* x = (const float*)d_in[0];
    const float2* tables = (const float2*)d_in[1];
    int npts = in_sizes[0] / 3;

    // Replicate numpy's RES computation bit-for-bit in float64 (same libm,
    // incl. numpy's pow shortcuts). RES is exactly integral at levels
    // 0,3,6,9,12,15, so independent recomputation risks off-by-one in floor.
    ResParams rp;
    double bb = exp((log(512.0) - log(16.0)) / 15.0);
    for (int l = 0; l < NGP_L; l++) {
        double p;
        if (l == 0)      p = 1.0;
        else if (l == 1) p = bb;
        else if (l == 2) p = bb * bb;
        else             p = pow(bb, (double)l);
        rp.r[l] = (float)floor(16.0 * p);
    }

    if (npts > BMAX) {
        int total = npts * 16;
        ngp_flat_kernel<<<(total + 255) / 256, 256>>>(x, tables, (float2*)d_out, rp, npts);
        return;
    }

    void* histAddr = nullptr;
    cudaGetSymbolAddress(&histAddr, g_hist);
    cudaMemsetAsync(histAddr, 0, NB * sizeof(unsigned));

    int blocks = (npts + 255) / 256;
    k_hist<<<blocks, 256>>>(x, npts);
    k_scan<<<1, 1024>>>();
    k_scatter<<<blocks, 256>>>(x, npts);
    k_main<<<blocks, 256>>>(tables, rp, npts);
    k_perm<<<(npts + 127) / 128, 128>>>((float*)d_out, npts);
}